// round 14
// baseline (speedup 1.0000x reference)
#include <cuda_runtime.h>
#include <cuda_bf16.h>
#include <mma.h>
#include <math.h>
#include <stdint.h>

using namespace nvcuda;

// ---------------- Fixed problem geometry ----------------
#define B_      64
#define N_      1024
#define E_      655360
#define H_      128
#define K1_     820
#define K2_     656
#define NODES1  (B_ * N_)    // 65536
#define NODES2  (B_ * K1_)   // 52480
#define NODES3  (B_ * K2_)   // 41984

// ---------------- Scratch (static device globals; no runtime alloc) ----------------
__device__ float g_s     [NODES1 * 128];
__device__ float g_h1    [NODES1 * 128];
__device__ float g_score1[NODES1];
__device__ int   g_perm1 [NODES2];
__device__ int   g_inv1  [NODES1];
__device__ float g_h1p   [NODES2 * 128];
__device__ float g_x1    [B_ * 256];
__device__ float g_s2    [NODES2 * 128];
__device__ float g_h2    [NODES2 * 128];
__device__ float g_score2[NODES2];
__device__ int   g_perm2 [NODES3];
__device__ float g_h2p   [NODES3 * 128];
__device__ float g_x2    [B_ * 256];
// transposed, bf16-split weights: [n=128][k=256] K-major (k contiguous)
__device__ __nv_bfloat16 g_wthi1[128 * 256];
__device__ __nv_bfloat16 g_wtlo1[128 * 256];
__device__ __nv_bfloat16 g_wthi2[128 * 256];
__device__ __nv_bfloat16 g_wtlo2[128 * 256];
// CSR scratch
__device__ int g_deg1   [NODES1];
__device__ int g_row1   [NODES1 + 1];
__device__ int g_cur1   [NODES1];
__device__ int g_csrc1  [E_];
__device__ int g_deg2   [NODES2];
__device__ int g_row2   [NODES2 + 1];
__device__ int g_cur2   [NODES2];
__device__ int g_csrc2  [E_];

// ---------------- CSR build: degree histograms ----------------
__global__ void deg1_kernel(const int* __restrict__ dst, int* __restrict__ deg)
{
    int e = blockIdx.x * blockDim.x + threadIdx.x;
    if (e < E_) atomicAdd(&deg[dst[e]], 1);
}
__global__ void deg2_kernel(const int* __restrict__ src, const int* __restrict__ dst,
                            const int* __restrict__ inv, int* __restrict__ deg)
{
    int e = blockIdx.x * blockDim.x + threadIdx.x;
    if (e >= E_) return;
    int ns = inv[src[e]], nd = inv[dst[e]];
    if (ns >= 0 && nd >= 0) atomicAdd(&deg[nd], 1);
}

// ---------------- single-block exclusive scan: rowptr + cursor init ----------------
__global__ __launch_bounds__(1024) void scan_kernel(const int* __restrict__ deg,
                                                    int* __restrict__ rowptr,
                                                    int* __restrict__ cursor, int n)
{
    __shared__ int tsum[1024];
    int tid = threadIdx.x;
    int per = (n + 1023) >> 10;
    int lo = tid * per;
    int hi = min(lo + per, n);
    int s = 0;
    for (int i = lo; i < hi; i++) s += deg[i];
    tsum[tid] = s;
    __syncthreads();
    for (int off = 1; off < 1024; off <<= 1) {
        int v = (tid >= off) ? tsum[tid - off] : 0;
        __syncthreads();
        tsum[tid] += v;
        __syncthreads();
    }
    int base = (tid > 0) ? tsum[tid - 1] : 0;
    for (int i = lo; i < hi; i++) {
        rowptr[i] = base;
        cursor[i] = base;
        base += deg[i];
    }
    if (tid == 1023) rowptr[n] = tsum[1023];
}

// ---------------- scatter edges into CSR ----------------
__global__ void scatter1_kernel(const int* __restrict__ src, const int* __restrict__ dst,
                                int* __restrict__ cursor, int* __restrict__ csrc)
{
    int e = blockIdx.x * blockDim.x + threadIdx.x;
    if (e >= E_) return;
    int p = atomicAdd(&cursor[dst[e]], 1);
    csrc[p] = src[e];
}
__global__ void scatter2_kernel(const int* __restrict__ src, const int* __restrict__ dst,
                                const int* __restrict__ inv,
                                int* __restrict__ cursor, int* __restrict__ csrc)
{
    int e = blockIdx.x * blockDim.x + threadIdx.x;
    if (e >= E_) return;
    int ns = inv[src[e]], nd = inv[dst[e]];
    if (ns < 0 || nd < 0) return;
    int p = atomicAdd(&cursor[nd], 1);
    csrc[p] = ns;
}

// ---------------- CSR aggregation + mean, warp per node (fuses meandiv; no memset) ------------
__global__ void agg_csr_kernel(const float* __restrict__ feat, const int* __restrict__ rowptr,
                               const int* __restrict__ csrc, float* __restrict__ s, int n)
{
    int g = blockIdx.x * blockDim.x + threadIdx.x;
    int node = g >> 5, lane = g & 31;
    if (node >= n) return;
    int beg = rowptr[node], end = rowptr[node + 1];
    float4 acc = make_float4(0.f, 0.f, 0.f, 0.f);
    for (int e = beg; e < end; e++) {
        int sn = csrc[e];
        float4 v = ((const float4*)(feat + (size_t)sn * 128))[lane];
        acc.x += v.x; acc.y += v.y; acc.z += v.z; acc.w += v.w;
    }
    float c = fmaxf((float)(end - beg), 1.0f);
    acc.x /= c; acc.y /= c; acc.z /= c; acc.w /= c;
    ((float4*)(s + (size_t)node * 128))[lane] = acc;
}

// ---------------- weight prep: Wt_hi/lo[n][k] = split(W[k][n]), [Wl;Wr] stacked ---------------
__global__ void prep_w_kernel(const float* __restrict__ Wl, const float* __restrict__ Wr,
                              __nv_bfloat16* __restrict__ hi, __nv_bfloat16* __restrict__ lo)
{
    int i = blockIdx.x * blockDim.x + threadIdx.x;  // 128*256
    if (i >= 128 * 256) return;
    int n = i >> 8, k = i & 255;
    float v = (k < 128) ? Wl[k * 128 + n] : Wr[(k - 128) * 128 + n];
    __nv_bfloat16 h = __float2bfloat16(v);
    hi[i] = h;
    lo[i] = __float2bfloat16(v - __bfloat162float(h));
}

// ---------------- wmma bf16 SAGE GEMM + fused score ------------------------------------------
// out = relu([mean|xin] @ [Wl;Wr] + bias); score = tanh(out . w / ||w||)
// 128x128 tile/CTA, 8 warps (4x2 of 32x64 warp tiles), K=256 in 4 chunks of 64.
// Split-bf16 3-product fp32 emulation: Ahi*Bhi + Ahi*Blo + Alo*Bhi.
#define LDA     72
#define SM_BIAS 0                        // 128 floats
#define SM_W    512                      // 128 floats
#define SM_AHI  1024
#define SM_ALO  (SM_AHI + 128 * LDA * 2)
#define SM_BHI  (SM_ALO + 128 * LDA * 2)
#define SM_BLO  (SM_BHI + 128 * LDA * 2)
#define SM_END  (SM_BLO + 128 * LDA * 2)     // 1024 + 73728 = 74752
#define SM_OUT  1024                     // reused post-mainloop: 128 x 132 f32
#define LDO     132

__global__ __launch_bounds__(256, 2)
void sage_wmma_kernel(const float* __restrict__ mean, const float* __restrict__ xin,
                      const __nv_bfloat16* __restrict__ wt_hi,
                      const __nv_bfloat16* __restrict__ wt_lo,
                      const float* __restrict__ bias, const float* __restrict__ pw,
                      float* __restrict__ outp, float* __restrict__ scoreo)
{
    extern __shared__ char smem[];
    float* sbias = (float*)(smem + SM_BIAS);
    float* sw    = (float*)(smem + SM_W);
    __nv_bfloat16* sAhi = (__nv_bfloat16*)(smem + SM_AHI);
    __nv_bfloat16* sAlo = (__nv_bfloat16*)(smem + SM_ALO);
    __nv_bfloat16* sBhi = (__nv_bfloat16*)(smem + SM_BHI);
    __nv_bfloat16* sBlo = (__nv_bfloat16*)(smem + SM_BLO);

    int tid = threadIdx.x;
    int warp = tid >> 5;
    int wy = warp >> 1;
    int wx = warp & 1;
    int row0 = blockIdx.x * 128;

    if (tid < 128) sbias[tid] = bias[tid];
    else if (tid < 256) sw[tid - 128] = pw[tid - 128];

    wmma::fragment<wmma::accumulator, 16, 16, 16, float> acc[2][4];
    #pragma unroll
    for (int mi = 0; mi < 2; mi++)
        #pragma unroll
        for (int nt = 0; nt < 4; nt++) wmma::fill_fragment(acc[mi][nt], 0.0f);

    #pragma unroll 1
    for (int chunk = 0; chunk < 4; chunk++) {
        const float* abase = (chunk < 2) ? mean : xin;
        int acol = (chunk & 1) * 64;
        #pragma unroll
        for (int s = tid; s < 1024; s += 256) {
            int r = s >> 3, kseg = s & 7;
            const float* ap = abase + (size_t)(row0 + r) * 128 + acol + kseg * 8;
            float4 v0 = *(const float4*)ap;
            float4 v1 = *(const float4*)(ap + 4);
            float vv[8] = {v0.x, v0.y, v0.z, v0.w, v1.x, v1.y, v1.z, v1.w};
            unsigned int Hh[4], Ll[4];
            #pragma unroll
            for (int i = 0; i < 4; i++) {
                __nv_bfloat16 h0 = __float2bfloat16(vv[2 * i]);
                __nv_bfloat16 h1 = __float2bfloat16(vv[2 * i + 1]);
                __nv_bfloat16 l0 = __float2bfloat16(vv[2 * i] - __bfloat162float(h0));
                __nv_bfloat16 l1 = __float2bfloat16(vv[2 * i + 1] - __bfloat162float(h1));
                Hh[i] = (unsigned int)__bfloat16_as_ushort(h0)
                      | ((unsigned int)__bfloat16_as_ushort(h1) << 16);
                Ll[i] = (unsigned int)__bfloat16_as_ushort(l0)
                      | ((unsigned int)__bfloat16_as_ushort(l1) << 16);
            }
            *(uint4*)(sAhi + r * LDA + kseg * 8) = make_uint4(Hh[0], Hh[1], Hh[2], Hh[3]);
            *(uint4*)(sAlo + r * LDA + kseg * 8) = make_uint4(Ll[0], Ll[1], Ll[2], Ll[3]);
        }
        #pragma unroll
        for (int s = tid; s < 1024; s += 256) {
            int n = s >> 3, kseg = s & 7;
            size_t gi = (size_t)n * 256 + chunk * 64 + kseg * 8;
            *(uint4*)(sBhi + n * LDA + kseg * 8) = *(const uint4*)(wt_hi + gi);
            *(uint4*)(sBlo + n * LDA + kseg * 8) = *(const uint4*)(wt_lo + gi);
        }
        __syncthreads();

        #pragma unroll
        for (int ks = 0; ks < 4; ks++) {
            wmma::fragment<wmma::matrix_a, 16, 16, 16, __nv_bfloat16, wmma::row_major> ahi[2], alo[2];
            #pragma unroll
            for (int mi = 0; mi < 2; mi++) {
                wmma::load_matrix_sync(ahi[mi], sAhi + (wy * 32 + mi * 16) * LDA + ks * 16, LDA);
                wmma::load_matrix_sync(alo[mi], sAlo + (wy * 32 + mi * 16) * LDA + ks * 16, LDA);
            }
            #pragma unroll
            for (int nt = 0; nt < 4; nt++) {
                wmma::fragment<wmma::matrix_b, 16, 16, 16, __nv_bfloat16, wmma::col_major> bhi, blo;
                wmma::load_matrix_sync(bhi, sBhi + (wx * 64 + nt * 16) * LDA + ks * 16, LDA);
                wmma::load_matrix_sync(blo, sBlo + (wx * 64 + nt * 16) * LDA + ks * 16, LDA);
                #pragma unroll
                for (int mi = 0; mi < 2; mi++) {
                    wmma::mma_sync(acc[mi][nt], ahi[mi], bhi, acc[mi][nt]);
                    wmma::mma_sync(acc[mi][nt], ahi[mi], blo, acc[mi][nt]);
                    wmma::mma_sync(acc[mi][nt], alo[mi], bhi, acc[mi][nt]);
                }
            }
        }
        __syncthreads();
    }

    // ---- epilogue: dump accs to SMEM; bias+relu; store; fused score ----
    float* sout = (float*)(smem + SM_OUT);
    #pragma unroll
    for (int mi = 0; mi < 2; mi++)
        #pragma unroll
        for (int nt = 0; nt < 4; nt++)
            wmma::store_matrix_sync(sout + (wy * 32 + mi * 16) * LDO + wx * 64 + nt * 16,
                                    acc[mi][nt], LDO, wmma::mem_row_major);
    __syncthreads();

    int tr = tid >> 1;
    int tc = (tid & 1) * 64;
    float dot = 0.0f, nrm = 0.0f;
    #pragma unroll
    for (int q = 0; q < 16; q++) {
        int col = tc + q * 4;
        float4 v = *(float4*)&sout[tr * LDO + col];
        float4 bb = *(float4*)&sbias[col];
        float4 wv = *(float4*)&sw[col];
        v.x = fmaxf(v.x + bb.x, 0.0f);
        v.y = fmaxf(v.y + bb.y, 0.0f);
        v.z = fmaxf(v.z + bb.z, 0.0f);
        v.w = fmaxf(v.w + bb.w, 0.0f);
        dot += v.x * wv.x + v.y * wv.y + v.z * wv.z + v.w * wv.w;
        nrm += wv.x * wv.x + wv.y * wv.y + wv.z * wv.z + wv.w * wv.w;
        *(float4*)&outp[(size_t)(row0 + tr) * 128 + col] = v;
    }
    dot += __shfl_xor_sync(0xFFFFFFFFu, dot, 1);
    nrm += __shfl_xor_sync(0xFFFFFFFFu, nrm, 1);
    if ((tid & 1) == 0) scoreo[row0 + tr] = tanhf(dot * rsqrtf(nrm));
}

// ---------------- TopK pool: per-graph bitonic sort (desc score, asc idx), compact by idx ----
__global__ __launch_bounds__(1024) void topk_kernel(
    const float* __restrict__ score, int* __restrict__ perm, int* __restrict__ inv,
    int n_per, int K)
{
    __shared__ unsigned long long keys[1024];
    __shared__ int keep[1024];
    __shared__ int scan[1024];
    int tid = threadIdx.x, b = blockIdx.x;

    float sc = (tid < n_per) ? score[b * n_per + tid] : __int_as_float(0xFF800000);
    unsigned int bits = __float_as_uint(sc);
    unsigned int u = (bits & 0x80000000u) ? ~bits : (bits | 0x80000000u);
    keys[tid] = ((unsigned long long)u << 32) | (unsigned int)(1023 - tid);
    keep[tid] = 0;
    __syncthreads();

    for (int k = 2; k <= 1024; k <<= 1) {
        for (int j = k >> 1; j > 0; j >>= 1) {
            int ixj = tid ^ j;
            if (ixj > tid) {
                unsigned long long a = keys[tid], c = keys[ixj];
                bool up = ((tid & k) == 0);
                bool sw = up ? (a < c) : (a > c);
                if (sw) { keys[tid] = c; keys[ixj] = a; }
            }
            __syncthreads();
        }
    }

    if (tid < K) {
        int idx = 1023 - (int)(keys[tid] & 0xFFFFFFFFu);
        keep[idx] = 1;
    }
    __syncthreads();

    int v = keep[tid];
    scan[tid] = v;
    __syncthreads();
    for (int off = 1; off < 1024; off <<= 1) {
        int t = (tid >= off) ? scan[tid - off] : 0;
        __syncthreads();
        scan[tid] += t;
        __syncthreads();
    }

    if (tid < n_per) {
        int old = b * n_per + tid;
        if (v) {
            int newid = b * K + (scan[tid] - 1);
            perm[newid] = old;
            if (inv) inv[old] = newid;
        } else if (inv) {
            inv[old] = -1;
        }
    }
}

// ---------------- gate: hp[new] = h[perm[new]] * score[perm[new]] -----------------------------
__global__ void gate_kernel(const float* __restrict__ h, const float* __restrict__ score,
                            const int* __restrict__ perm, float* __restrict__ hp, int total)
{
    int g = blockIdx.x * blockDim.x + threadIdx.x;
    int nid = g >> 5, lane = g & 31;
    if (nid >= total) return;
    int old = perm[nid];
    float sc = score[old];
    float4 v = ((const float4*)(h + (size_t)old * 128))[lane];
    v.x *= sc; v.y *= sc; v.z *= sc; v.w *= sc;
    ((float4*)(hp + (size_t)nid * 128))[lane] = v;
}

// ---------------- readout: [mean over K | max over K] per graph ------------------------------
__global__ void readout_kernel(const float* __restrict__ hp, float* __restrict__ xout, int K)
{
    __shared__ float ss[4][128], sm[4][128];
    int b = blockIdx.x;
    int tid = threadIdx.x;          // 512 threads
    int f = tid & 127, ty = tid >> 7;
    float sum = 0.0f, mx = __int_as_float(0xFF800000);
    for (int r = ty; r < K; r += 4) {
        float v = hp[((size_t)(b * K + r)) * 128 + f];
        sum += v;
        mx = fmaxf(mx, v);
    }
    ss[ty][f] = sum; sm[ty][f] = mx;
    __syncthreads();
    if (ty == 0) {
        float s = ss[0][f] + ss[1][f] + ss[2][f] + ss[3][f];
        float m = fmaxf(fmaxf(sm[0][f], sm[1][f]), fmaxf(sm[2][f], sm[3][f]));
        xout[b * 256 + f] = s / (float)K;
        xout[b * 256 + 128 + f] = m;
    }
}

// ---------------- final MLP: out = relu((x1+x2)@fW1+fb1) @ fW2 + fb2 --------------------------
__global__ void mlp_kernel(const float* __restrict__ x1, const float* __restrict__ x2,
                           const float* __restrict__ fW1, const float* __restrict__ fb1,
                           const float* __restrict__ fW2, const float* __restrict__ fb2,
                           float* __restrict__ out)
{
    __shared__ float row[256];
    __shared__ float zs[128];
    int b = blockIdx.x, t = threadIdx.x;
    row[t]       = x1[b * 256 + t]       + x2[b * 256 + t];
    row[t + 128] = x1[b * 256 + 128 + t] + x2[b * 256 + 128 + t];
    __syncthreads();
    float acc = fb1[t];
    #pragma unroll 8
    for (int k = 0; k < 256; k++) acc += row[k] * fW1[k * 128 + t];
    zs[t] = fmaxf(acc, 0.0f);
    __syncthreads();
    if (t < 10) {
        float o = fb2[t];
        #pragma unroll 8
        for (int k = 0; k < 128; k++) o += zs[k] * fW2[k * 10 + t];
        out[b * 10 + t] = o;
    }
}

// ---------------- host orchestration ----------------------------------------------------------
extern "C" void kernel_launch(void* const* d_in, const int* in_sizes, int n_in,
                              void* d_out, int out_size)
{
    (void)in_sizes; (void)n_in; (void)out_size;
    const float* x   = (const float*)d_in[0];
    const int*   ei  = (const int*)d_in[1];
    const float* Wl1 = (const float*)d_in[3];
    const float* bl1 = (const float*)d_in[4];
    const float* Wr1 = (const float*)d_in[5];
    const float* Wl2 = (const float*)d_in[6];
    const float* bl2 = (const float*)d_in[7];
    const float* Wr2 = (const float*)d_in[8];
    const float* pw1 = (const float*)d_in[9];
    const float* pw2 = (const float*)d_in[10];
    const float* fW1 = (const float*)d_in[11];
    const float* fb1 = (const float*)d_in[12];
    const float* fW2 = (const float*)d_in[13];
    const float* fb2 = (const float*)d_in[14];
    float* out = (float*)d_out;

    const int* src = ei;
    const int* dst = ei + E_;

    float *ps, *ph1, *psc1, *ph1p, *px1, *ps2, *ph2, *psc2, *ph2p, *px2;
    int *pperm1, *pinv1, *pperm2;
    int *pdeg1, *prow1, *pcur1, *pcsrc1, *pdeg2, *prow2, *pcur2, *pcsrc2;
    __nv_bfloat16 *pwh1, *pwl1_, *pwh2, *pwl2_;
    cudaGetSymbolAddress((void**)&ps,     g_s);
    cudaGetSymbolAddress((void**)&ph1,    g_h1);
    cudaGetSymbolAddress((void**)&psc1,   g_score1);
    cudaGetSymbolAddress((void**)&pperm1, g_perm1);
    cudaGetSymbolAddress((void**)&pinv1,  g_inv1);
    cudaGetSymbolAddress((void**)&ph1p,   g_h1p);
    cudaGetSymbolAddress((void**)&px1,    g_x1);
    cudaGetSymbolAddress((void**)&ps2,    g_s2);
    cudaGetSymbolAddress((void**)&ph2,    g_h2);
    cudaGetSymbolAddress((void**)&psc2,   g_score2);
    cudaGetSymbolAddress((void**)&pperm2, g_perm2);
    cudaGetSymbolAddress((void**)&ph2p,   g_h2p);
    cudaGetSymbolAddress((void**)&px2,    g_x2);
    cudaGetSymbolAddress((void**)&pwh1,   g_wthi1);
    cudaGetSymbolAddress((void**)&pwl1_,  g_wtlo1);
    cudaGetSymbolAddress((void**)&pwh2,   g_wthi2);
    cudaGetSymbolAddress((void**)&pwl2_,  g_wtlo2);
    cudaGetSymbolAddress((void**)&pdeg1,  g_deg1);
    cudaGetSymbolAddress((void**)&prow1,  g_row1);
    cudaGetSymbolAddress((void**)&pcur1,  g_cur1);
    cudaGetSymbolAddress((void**)&pcsrc1, g_csrc1);
    cudaGetSymbolAddress((void**)&pdeg2,  g_deg2);
    cudaGetSymbolAddress((void**)&prow2,  g_row2);
    cudaGetSymbolAddress((void**)&pcur2,  g_cur2);
    cudaGetSymbolAddress((void**)&pcsrc2, g_csrc2);

    cudaFuncSetAttribute(sage_wmma_kernel,
                         cudaFuncAttributeMaxDynamicSharedMemorySize, SM_END);

    // zero degree histograms (tiny)
    cudaMemsetAsync(pdeg1, 0, sizeof(int) * NODES1);
    cudaMemsetAsync(pdeg2, 0, sizeof(int) * NODES2);

    // weight prep
    prep_w_kernel<<<128, 256>>>(Wl1, Wr1, pwh1, pwl1_);
    prep_w_kernel<<<128, 256>>>(Wl2, Wr2, pwh2, pwl2_);

    // ---- layer 1: CSR build + gather-agg (fused mean) ----
    deg1_kernel<<<(E_ + 255) / 256, 256>>>(dst, pdeg1);
    scan_kernel<<<1, 1024>>>(pdeg1, prow1, pcur1, NODES1);
    scatter1_kernel<<<(E_ + 255) / 256, 256>>>(src, dst, pcur1, pcsrc1);
    agg_csr_kernel<<<(NODES1 * 32) / 256, 256>>>(x, prow1, pcsrc1, ps, NODES1);
    sage_wmma_kernel<<<NODES1 / 128, 256, SM_END>>>(ps, x, pwh1, pwl1_, bl1, pw1, ph1, psc1);
    topk_kernel<<<B_, 1024>>>(psc1, pperm1, pinv1, N_, K1_);
    gate_kernel<<<(NODES2 * 32) / 256, 256>>>(ph1, psc1, pperm1, ph1p, NODES2);
    readout_kernel<<<B_, 512>>>(ph1p, px1, K1_);

    // ---- layer 2: CSR build (masked+relabelled) + gather-agg ----
    deg2_kernel<<<(E_ + 255) / 256, 256>>>(src, dst, pinv1, pdeg2);
    scan_kernel<<<1, 1024>>>(pdeg2, prow2, pcur2, NODES2);
    scatter2_kernel<<<(E_ + 255) / 256, 256>>>(src, dst, pinv1, pcur2, pcsrc2);
    agg_csr_kernel<<<(NODES2 * 32) / 256, 256>>>(ph1p, prow2, pcsrc2, ps2, NODES2);
    sage_wmma_kernel<<<NODES2 / 128, 256, SM_END>>>(ps2, ph1p, pwh2, pwl2_, bl2, pw2, ph2, psc2);
    topk_kernel<<<B_, 1024>>>(psc2, pperm2, (int*)0, K1_, K2_);
    gate_kernel<<<(NODES3 * 32) / 256, 256>>>(ph2, psc2, pperm2, ph2p, NODES3);
    readout_kernel<<<B_, 512>>>(ph2p, px2, K2_);

    // ---- head ----
    mlp_kernel<<<B_, 128>>>(px1, px2, fW1, fb1, fW2, fb2, out);
}

// round 15
// speedup vs baseline: 1.7283x; 1.7283x over previous
#include <cuda_runtime.h>
#include <cuda_bf16.h>
#include <mma.h>
#include <math.h>
#include <stdint.h>

using namespace nvcuda;

// ---------------- Fixed problem geometry ----------------
#define B_      64
#define N_      1024
#define E_      655360
#define H_      128
#define K1_     820
#define K2_     656
#define NODES1  (B_ * N_)    // 65536
#define NODES2  (B_ * K1_)   // 52480
#define NODES3  (B_ * K2_)   // 41984

// ---------------- Scratch (static device globals; no runtime alloc) ----------------
__device__ float g_s     [NODES1 * 128];
__device__ float g_h1    [NODES1 * 128];
__device__ float g_score1[NODES1];
__device__ int   g_perm1 [NODES2];
__device__ int   g_inv1  [NODES1];
__device__ float g_h1p   [NODES2 * 128];
__device__ float g_x1    [B_ * 256];
__device__ float g_s2    [NODES2 * 128];
__device__ float g_h2    [NODES2 * 128];
__device__ float g_score2[NODES2];
__device__ int   g_perm2 [NODES3];
__device__ float g_h2p   [NODES3 * 128];
__device__ float g_x2    [B_ * 256];
// transposed, bf16-split weights: [n=128][k=256] K-major (k contiguous)
__device__ __nv_bfloat16 g_wthi1[128 * 256];
__device__ __nv_bfloat16 g_wtlo1[128 * 256];
__device__ __nv_bfloat16 g_wthi2[128 * 256];
__device__ __nv_bfloat16 g_wtlo2[128 * 256];
// CSR scratch
__device__ int g_deg1   [NODES1];
__device__ int g_row1   [NODES1];
__device__ int g_cur1   [NODES1];
__device__ int g_csrc1  [E_];
__device__ int g_deg2   [NODES2];
__device__ int g_row2   [NODES2];
__device__ int g_cur2   [NODES2];
__device__ int g_csrc2  [E_];
__device__ int g_ctr1;
__device__ int g_ctr2;

// ---------------- CSR build: degree histograms ----------------
__global__ void deg1_kernel(const int* __restrict__ dst, int* __restrict__ deg)
{
    int e = blockIdx.x * blockDim.x + threadIdx.x;
    if (e < E_) atomicAdd(&deg[dst[e]], 1);
}
__global__ void deg2_kernel(const int* __restrict__ src, const int* __restrict__ dst,
                            const int* __restrict__ inv, int* __restrict__ deg)
{
    int e = blockIdx.x * blockDim.x + threadIdx.x;
    if (e >= E_) return;
    int ns = inv[src[e]], nd = inv[dst[e]];
    if (ns >= 0 && nd >= 0) atomicAdd(&deg[nd], 1);
}

// ---------------- segment allocator: per-block scan + single global atomic -------------------
// rowptr[i] gets a contiguous segment of size deg[i]; order across blocks irrelevant.
__global__ __launch_bounds__(256) void alloc_kernel(const int* __restrict__ deg,
                                                    int* __restrict__ rowptr,
                                                    int* __restrict__ cursor,
                                                    int n, int* __restrict__ ctr)
{
    __shared__ int sdata[256];
    __shared__ int sbase;
    int tid = threadIdx.x;
    int i = blockIdx.x * 256 + tid;
    int d = (i < n) ? deg[i] : 0;
    sdata[tid] = d;
    __syncthreads();
    #pragma unroll
    for (int off = 1; off < 256; off <<= 1) {
        int v = (tid >= off) ? sdata[tid - off] : 0;
        __syncthreads();
        sdata[tid] += v;
        __syncthreads();
    }
    if (tid == 255) sbase = atomicAdd(ctr, sdata[255]);
    __syncthreads();
    if (i < n) {
        int p = sbase + sdata[tid] - d;   // exclusive position within block + block base
        rowptr[i] = p;
        cursor[i] = p;
    }
}

// ---------------- scatter edges into CSR ----------------
__global__ void scatter1_kernel(const int* __restrict__ src, const int* __restrict__ dst,
                                int* __restrict__ cursor, int* __restrict__ csrc)
{
    int e = blockIdx.x * blockDim.x + threadIdx.x;
    if (e >= E_) return;
    int p = atomicAdd(&cursor[dst[e]], 1);
    csrc[p] = src[e];
}
__global__ void scatter2_kernel(const int* __restrict__ src, const int* __restrict__ dst,
                                const int* __restrict__ inv,
                                int* __restrict__ cursor, int* __restrict__ csrc)
{
    int e = blockIdx.x * blockDim.x + threadIdx.x;
    if (e >= E_) return;
    int ns = inv[src[e]], nd = inv[dst[e]];
    if (ns < 0 || nd < 0) return;
    int p = atomicAdd(&cursor[nd], 1);
    csrc[p] = ns;
}

// ---------------- CSR aggregation + mean, warp per node (fused meandiv; no memset) ------------
__global__ void agg_csr_kernel(const float* __restrict__ feat, const int* __restrict__ rowptr,
                               const int* __restrict__ deg, const int* __restrict__ csrc,
                               float* __restrict__ s, int n)
{
    int g = blockIdx.x * blockDim.x + threadIdx.x;
    int node = g >> 5, lane = g & 31;
    if (node >= n) return;
    int beg = rowptr[node];
    int cnt = deg[node];
    float4 acc = make_float4(0.f, 0.f, 0.f, 0.f);
    for (int e = beg; e < beg + cnt; e++) {
        int sn = csrc[e];
        float4 v = ((const float4*)(feat + (size_t)sn * 128))[lane];
        acc.x += v.x; acc.y += v.y; acc.z += v.z; acc.w += v.w;
    }
    float c = fmaxf((float)cnt, 1.0f);
    acc.x /= c; acc.y /= c; acc.z /= c; acc.w /= c;
    ((float4*)(s + (size_t)node * 128))[lane] = acc;
}

// ---------------- weight prep: Wt_hi/lo[n][k] = split(W[k][n]), [Wl;Wr] stacked ---------------
__global__ void prep_w_kernel(const float* __restrict__ Wl, const float* __restrict__ Wr,
                              __nv_bfloat16* __restrict__ hi, __nv_bfloat16* __restrict__ lo)
{
    int i = blockIdx.x * blockDim.x + threadIdx.x;  // 128*256
    if (i >= 128 * 256) return;
    int n = i >> 8, k = i & 255;
    float v = (k < 128) ? Wl[k * 128 + n] : Wr[(k - 128) * 128 + n];
    __nv_bfloat16 h = __float2bfloat16(v);
    hi[i] = h;
    lo[i] = __float2bfloat16(v - __bfloat162float(h));
}

// ---------------- wmma bf16 SAGE GEMM + fused score ------------------------------------------
// out = relu([mean|xin] @ [Wl;Wr] + bias); score = tanh(out . w / ||w||)
// 128x128 tile/CTA, 8 warps (4x2 of 32x64 warp tiles), K=256 in 4 chunks of 64.
// Split-bf16 3-product fp32 emulation: Ahi*Bhi + Ahi*Blo + Alo*Bhi.
#define LDA     72
#define SM_BIAS 0                        // 128 floats
#define SM_W    512                      // 128 floats
#define SM_AHI  1024
#define SM_ALO  (SM_AHI + 128 * LDA * 2)
#define SM_BHI  (SM_ALO + 128 * LDA * 2)
#define SM_BLO  (SM_BHI + 128 * LDA * 2)
#define SM_END  (SM_BLO + 128 * LDA * 2)     // 1024 + 73728 = 74752
#define SM_OUT  1024                     // reused post-mainloop: 128 x 132 f32
#define LDO     132

__global__ __launch_bounds__(256, 2)
void sage_wmma_kernel(const float* __restrict__ mean, const float* __restrict__ xin,
                      const __nv_bfloat16* __restrict__ wt_hi,
                      const __nv_bfloat16* __restrict__ wt_lo,
                      const float* __restrict__ bias, const float* __restrict__ pw,
                      float* __restrict__ outp, float* __restrict__ scoreo)
{
    extern __shared__ char smem[];
    float* sbias = (float*)(smem + SM_BIAS);
    float* sw    = (float*)(smem + SM_W);
    __nv_bfloat16* sAhi = (__nv_bfloat16*)(smem + SM_AHI);
    __nv_bfloat16* sAlo = (__nv_bfloat16*)(smem + SM_ALO);
    __nv_bfloat16* sBhi = (__nv_bfloat16*)(smem + SM_BHI);
    __nv_bfloat16* sBlo = (__nv_bfloat16*)(smem + SM_BLO);

    int tid = threadIdx.x;
    int warp = tid >> 5;
    int wy = warp >> 1;
    int wx = warp & 1;
    int row0 = blockIdx.x * 128;

    if (tid < 128) sbias[tid] = bias[tid];
    else if (tid < 256) sw[tid - 128] = pw[tid - 128];

    wmma::fragment<wmma::accumulator, 16, 16, 16, float> acc[2][4];
    #pragma unroll
    for (int mi = 0; mi < 2; mi++)
        #pragma unroll
        for (int nt = 0; nt < 4; nt++) wmma::fill_fragment(acc[mi][nt], 0.0f);

    #pragma unroll 1
    for (int chunk = 0; chunk < 4; chunk++) {
        const float* abase = (chunk < 2) ? mean : xin;
        int acol = (chunk & 1) * 64;
        #pragma unroll
        for (int s = tid; s < 1024; s += 256) {
            int r = s >> 3, kseg = s & 7;
            const float* ap = abase + (size_t)(row0 + r) * 128 + acol + kseg * 8;
            float4 v0 = *(const float4*)ap;
            float4 v1 = *(const float4*)(ap + 4);
            float vv[8] = {v0.x, v0.y, v0.z, v0.w, v1.x, v1.y, v1.z, v1.w};
            unsigned int Hh[4], Ll[4];
            #pragma unroll
            for (int i = 0; i < 4; i++) {
                __nv_bfloat16 h0 = __float2bfloat16(vv[2 * i]);
                __nv_bfloat16 h1 = __float2bfloat16(vv[2 * i + 1]);
                __nv_bfloat16 l0 = __float2bfloat16(vv[2 * i] - __bfloat162float(h0));
                __nv_bfloat16 l1 = __float2bfloat16(vv[2 * i + 1] - __bfloat162float(h1));
                Hh[i] = (unsigned int)__bfloat16_as_ushort(h0)
                      | ((unsigned int)__bfloat16_as_ushort(h1) << 16);
                Ll[i] = (unsigned int)__bfloat16_as_ushort(l0)
                      | ((unsigned int)__bfloat16_as_ushort(l1) << 16);
            }
            *(uint4*)(sAhi + r * LDA + kseg * 8) = make_uint4(Hh[0], Hh[1], Hh[2], Hh[3]);
            *(uint4*)(sAlo + r * LDA + kseg * 8) = make_uint4(Ll[0], Ll[1], Ll[2], Ll[3]);
        }
        #pragma unroll
        for (int s = tid; s < 1024; s += 256) {
            int n = s >> 3, kseg = s & 7;
            size_t gi = (size_t)n * 256 + chunk * 64 + kseg * 8;
            *(uint4*)(sBhi + n * LDA + kseg * 8) = *(const uint4*)(wt_hi + gi);
            *(uint4*)(sBlo + n * LDA + kseg * 8) = *(const uint4*)(wt_lo + gi);
        }
        __syncthreads();

        #pragma unroll
        for (int ks = 0; ks < 4; ks++) {
            wmma::fragment<wmma::matrix_a, 16, 16, 16, __nv_bfloat16, wmma::row_major> ahi[2], alo[2];
            #pragma unroll
            for (int mi = 0; mi < 2; mi++) {
                wmma::load_matrix_sync(ahi[mi], sAhi + (wy * 32 + mi * 16) * LDA + ks * 16, LDA);
                wmma::load_matrix_sync(alo[mi], sAlo + (wy * 32 + mi * 16) * LDA + ks * 16, LDA);
            }
            #pragma unroll
            for (int nt = 0; nt < 4; nt++) {
                wmma::fragment<wmma::matrix_b, 16, 16, 16, __nv_bfloat16, wmma::col_major> bhi, blo;
                wmma::load_matrix_sync(bhi, sBhi + (wx * 64 + nt * 16) * LDA + ks * 16, LDA);
                wmma::load_matrix_sync(blo, sBlo + (wx * 64 + nt * 16) * LDA + ks * 16, LDA);
                #pragma unroll
                for (int mi = 0; mi < 2; mi++) {
                    wmma::mma_sync(acc[mi][nt], ahi[mi], bhi, acc[mi][nt]);
                    wmma::mma_sync(acc[mi][nt], ahi[mi], blo, acc[mi][nt]);
                    wmma::mma_sync(acc[mi][nt], alo[mi], bhi, acc[mi][nt]);
                }
            }
        }
        __syncthreads();
    }

    // ---- epilogue: dump accs to SMEM; bias+relu; store; fused score ----
    float* sout = (float*)(smem + SM_OUT);
    #pragma unroll
    for (int mi = 0; mi < 2; mi++)
        #pragma unroll
        for (int nt = 0; nt < 4; nt++)
            wmma::store_matrix_sync(sout + (wy * 32 + mi * 16) * LDO + wx * 64 + nt * 16,
                                    acc[mi][nt], LDO, wmma::mem_row_major);
    __syncthreads();

    int tr = tid >> 1;
    int tc = (tid & 1) * 64;
    float dot = 0.0f, nrm = 0.0f;
    #pragma unroll
    for (int q = 0; q < 16; q++) {
        int col = tc + q * 4;
        float4 v = *(float4*)&sout[tr * LDO + col];
        float4 bb = *(float4*)&sbias[col];
        float4 wv = *(float4*)&sw[col];
        v.x = fmaxf(v.x + bb.x, 0.0f);
        v.y = fmaxf(v.y + bb.y, 0.0f);
        v.z = fmaxf(v.z + bb.z, 0.0f);
        v.w = fmaxf(v.w + bb.w, 0.0f);
        dot += v.x * wv.x + v.y * wv.y + v.z * wv.z + v.w * wv.w;
        nrm += wv.x * wv.x + wv.y * wv.y + wv.z * wv.z + wv.w * wv.w;
        *(float4*)&outp[(size_t)(row0 + tr) * 128 + col] = v;
    }
    dot += __shfl_xor_sync(0xFFFFFFFFu, dot, 1);
    nrm += __shfl_xor_sync(0xFFFFFFFFu, nrm, 1);
    if ((tid & 1) == 0) scoreo[row0 + tr] = tanhf(dot * rsqrtf(nrm));
}

// ---------------- TopK pool: per-graph bitonic sort (desc score, asc idx), compact by idx ----
__global__ __launch_bounds__(1024) void topk_kernel(
    const float* __restrict__ score, int* __restrict__ perm, int* __restrict__ inv,
    int n_per, int K)
{
    __shared__ unsigned long long keys[1024];
    __shared__ int keep[1024];
    __shared__ int scan[1024];
    int tid = threadIdx.x, b = blockIdx.x;

    float sc = (tid < n_per) ? score[b * n_per + tid] : __int_as_float(0xFF800000);
    unsigned int bits = __float_as_uint(sc);
    unsigned int u = (bits & 0x80000000u) ? ~bits : (bits | 0x80000000u);
    keys[tid] = ((unsigned long long)u << 32) | (unsigned int)(1023 - tid);
    keep[tid] = 0;
    __syncthreads();

    for (int k = 2; k <= 1024; k <<= 1) {
        for (int j = k >> 1; j > 0; j >>= 1) {
            int ixj = tid ^ j;
            if (ixj > tid) {
                unsigned long long a = keys[tid], c = keys[ixj];
                bool up = ((tid & k) == 0);
                bool sw = up ? (a < c) : (a > c);
                if (sw) { keys[tid] = c; keys[ixj] = a; }
            }
            __syncthreads();
        }
    }

    if (tid < K) {
        int idx = 1023 - (int)(keys[tid] & 0xFFFFFFFFu);
        keep[idx] = 1;
    }
    __syncthreads();

    int v = keep[tid];
    scan[tid] = v;
    __syncthreads();
    for (int off = 1; off < 1024; off <<= 1) {
        int t = (tid >= off) ? scan[tid - off] : 0;
        __syncthreads();
        scan[tid] += t;
        __syncthreads();
    }

    if (tid < n_per) {
        int old = b * n_per + tid;
        if (v) {
            int newid = b * K + (scan[tid] - 1);
            perm[newid] = old;
            if (inv) inv[old] = newid;
        } else if (inv) {
            inv[old] = -1;
        }
    }
}

// ---------------- gate: hp[new] = h[perm[new]] * score[perm[new]] -----------------------------
__global__ void gate_kernel(const float* __restrict__ h, const float* __restrict__ score,
                            const int* __restrict__ perm, float* __restrict__ hp, int total)
{
    int g = blockIdx.x * blockDim.x + threadIdx.x;
    int nid = g >> 5, lane = g & 31;
    if (nid >= total) return;
    int old = perm[nid];
    float sc = score[old];
    float4 v = ((const float4*)(h + (size_t)old * 128))[lane];
    v.x *= sc; v.y *= sc; v.z *= sc; v.w *= sc;
    ((float4*)(hp + (size_t)nid * 128))[lane] = v;
}

// ---------------- readout: [mean over K | max over K] per graph ------------------------------
__global__ void readout_kernel(const float* __restrict__ hp, float* __restrict__ xout, int K)
{
    __shared__ float ss[4][128], sm[4][128];
    int b = blockIdx.x;
    int tid = threadIdx.x;          // 512 threads
    int f = tid & 127, ty = tid >> 7;
    float sum = 0.0f, mx = __int_as_float(0xFF800000);
    for (int r = ty; r < K; r += 4) {
        float v = hp[((size_t)(b * K + r)) * 128 + f];
        sum += v;
        mx = fmaxf(mx, v);
    }
    ss[ty][f] = sum; sm[ty][f] = mx;
    __syncthreads();
    if (ty == 0) {
        float s = ss[0][f] + ss[1][f] + ss[2][f] + ss[3][f];
        float m = fmaxf(fmaxf(sm[0][f], sm[1][f]), fmaxf(sm[2][f], sm[3][f]));
        xout[b * 256 + f] = s / (float)K;
        xout[b * 256 + 128 + f] = m;
    }
}

// ---------------- final MLP: out = relu((x1+x2)@fW1+fb1) @ fW2 + fb2 --------------------------
__global__ void mlp_kernel(const float* __restrict__ x1, const float* __restrict__ x2,
                           const float* __restrict__ fW1, const float* __restrict__ fb1,
                           const float* __restrict__ fW2, const float* __restrict__ fb2,
                           float* __restrict__ out)
{
    __shared__ float row[256];
    __shared__ float zs[128];
    int b = blockIdx.x, t = threadIdx.x;
    row[t]       = x1[b * 256 + t]       + x2[b * 256 + t];
    row[t + 128] = x1[b * 256 + 128 + t] + x2[b * 256 + 128 + t];
    __syncthreads();
    float acc = fb1[t];
    #pragma unroll 8
    for (int k = 0; k < 256; k++) acc += row[k] * fW1[k * 128 + t];
    zs[t] = fmaxf(acc, 0.0f);
    __syncthreads();
    if (t < 10) {
        float o = fb2[t];
        #pragma unroll 8
        for (int k = 0; k < 128; k++) o += zs[k] * fW2[k * 10 + t];
        out[b * 10 + t] = o;
    }
}

// ---------------- host orchestration ----------------------------------------------------------
extern "C" void kernel_launch(void* const* d_in, const int* in_sizes, int n_in,
                              void* d_out, int out_size)
{
    (void)in_sizes; (void)n_in; (void)out_size;
    const float* x   = (const float*)d_in[0];
    const int*   ei  = (const int*)d_in[1];
    const float* Wl1 = (const float*)d_in[3];
    const float* bl1 = (const float*)d_in[4];
    const float* Wr1 = (const float*)d_in[5];
    const float* Wl2 = (const float*)d_in[6];
    const float* bl2 = (const float*)d_in[7];
    const float* Wr2 = (const float*)d_in[8];
    const float* pw1 = (const float*)d_in[9];
    const float* pw2 = (const float*)d_in[10];
    const float* fW1 = (const float*)d_in[11];
    const float* fb1 = (const float*)d_in[12];
    const float* fW2 = (const float*)d_in[13];
    const float* fb2 = (const float*)d_in[14];
    float* out = (float*)d_out;

    const int* src = ei;
    const int* dst = ei + E_;

    float *ps, *ph1, *psc1, *ph1p, *px1, *ps2, *ph2, *psc2, *ph2p, *px2;
    int *pperm1, *pinv1, *pperm2;
    int *pdeg1, *prow1, *pcur1, *pcsrc1, *pdeg2, *prow2, *pcur2, *pcsrc2, *pctr1, *pctr2;
    __nv_bfloat16 *pwh1, *pwl1_, *pwh2, *pwl2_;
    cudaGetSymbolAddress((void**)&ps,     g_s);
    cudaGetSymbolAddress((void**)&ph1,    g_h1);
    cudaGetSymbolAddress((void**)&psc1,   g_score1);
    cudaGetSymbolAddress((void**)&pperm1, g_perm1);
    cudaGetSymbolAddress((void**)&pinv1,  g_inv1);
    cudaGetSymbolAddress((void**)&ph1p,   g_h1p);
    cudaGetSymbolAddress((void**)&px1,    g_x1);
    cudaGetSymbolAddress((void**)&ps2,    g_s2);
    cudaGetSymbolAddress((void**)&ph2,    g_h2);
    cudaGetSymbolAddress((void**)&psc2,   g_score2);
    cudaGetSymbolAddress((void**)&pperm2, g_perm2);
    cudaGetSymbolAddress((void**)&ph2p,   g_h2p);
    cudaGetSymbolAddress((void**)&px2,    g_x2);
    cudaGetSymbolAddress((void**)&pwh1,   g_wthi1);
    cudaGetSymbolAddress((void**)&pwl1_,  g_wtlo1);
    cudaGetSymbolAddress((void**)&pwh2,   g_wthi2);
    cudaGetSymbolAddress((void**)&pwl2_,  g_wtlo2);
    cudaGetSymbolAddress((void**)&pdeg1,  g_deg1);
    cudaGetSymbolAddress((void**)&prow1,  g_row1);
    cudaGetSymbolAddress((void**)&pcur1,  g_cur1);
    cudaGetSymbolAddress((void**)&pcsrc1, g_csrc1);
    cudaGetSymbolAddress((void**)&pdeg2,  g_deg2);
    cudaGetSymbolAddress((void**)&prow2,  g_row2);
    cudaGetSymbolAddress((void**)&pcur2,  g_cur2);
    cudaGetSymbolAddress((void**)&pcsrc2, g_csrc2);
    cudaGetSymbolAddress((void**)&pctr1,  g_ctr1);
    cudaGetSymbolAddress((void**)&pctr2,  g_ctr2);

    cudaFuncSetAttribute(sage_wmma_kernel,
                         cudaFuncAttributeMaxDynamicSharedMemorySize, SM_END);

    // zero degree histograms + segment counters (tiny)
    cudaMemsetAsync(pdeg1, 0, sizeof(int) * NODES1);
    cudaMemsetAsync(pdeg2, 0, sizeof(int) * NODES2);
    cudaMemsetAsync(pctr1, 0, sizeof(int));
    cudaMemsetAsync(pctr2, 0, sizeof(int));

    // weight prep
    prep_w_kernel<<<128, 256>>>(Wl1, Wr1, pwh1, pwl1_);
    prep_w_kernel<<<128, 256>>>(Wl2, Wr2, pwh2, pwl2_);

    // ---- layer 1: CSR build (no scan: block-aggregated segment allocator) + gather-agg ----
    deg1_kernel<<<(E_ + 255) / 256, 256>>>(dst, pdeg1);
    alloc_kernel<<<(NODES1 + 255) / 256, 256>>>(pdeg1, prow1, pcur1, NODES1, pctr1);
    scatter1_kernel<<<(E_ + 255) / 256, 256>>>(src, dst, pcur1, pcsrc1);
    agg_csr_kernel<<<(NODES1 * 32) / 256, 256>>>(x, prow1, pdeg1, pcsrc1, ps, NODES1);
    sage_wmma_kernel<<<NODES1 / 128, 256, SM_END>>>(ps, x, pwh1, pwl1_, bl1, pw1, ph1, psc1);
    topk_kernel<<<B_, 1024>>>(psc1, pperm1, pinv1, N_, K1_);
    gate_kernel<<<(NODES2 * 32) / 256, 256>>>(ph1, psc1, pperm1, ph1p, NODES2);
    readout_kernel<<<B_, 512>>>(ph1p, px1, K1_);

    // ---- layer 2: CSR build (masked+relabelled) + gather-agg ----
    deg2_kernel<<<(E_ + 255) / 256, 256>>>(src, dst, pinv1, pdeg2);
    alloc_kernel<<<(NODES2 + 255) / 256, 256>>>(pdeg2, prow2, pcur2, NODES2, pctr2);
    scatter2_kernel<<<(E_ + 255) / 256, 256>>>(src, dst, pinv1, pcur2, pcsrc2);
    agg_csr_kernel<<<(NODES2 * 32) / 256, 256>>>(ph1p, prow2, pdeg2, pcsrc2, ps2, NODES2);
    sage_wmma_kernel<<<NODES2 / 128, 256, SM_END>>>(ps2, ph1p, pwh2, pwl2_, bl2, pw2, ph2, psc2);
    topk_kernel<<<B_, 1024>>>(psc2, pperm2, (int*)0, K1_, K2_);
    gate_kernel<<<(NODES3 * 32) / 256, 256>>>(ph2, psc2, pperm2, ph2p, NODES3);
    readout_kernel<<<B_, 512>>>(ph2p, px2, K2_);

    // ---- head ----
    mlp_kernel<<<B_, 128>>>(px1, px2, fW1, fb1, fW2, fb2, out);
}

// round 16
// speedup vs baseline: 1.7447x; 1.0095x over previous
#include <cuda_runtime.h>
#include <cuda_bf16.h>
#include <mma.h>
#include <math.h>
#include <stdint.h>

using namespace nvcuda;

// ---------------- Fixed problem geometry ----------------
#define B_      64
#define N_      1024
#define E_      655360
#define H_      128
#define K1_     820
#define K2_     656
#define NODES1  (B_ * N_)    // 65536
#define NODES2  (B_ * K1_)   // 52480
#define NODES3  (B_ * K2_)   // 41984

// ---------------- Scratch (static device globals; no runtime alloc) ----------------
__device__ float g_s     [NODES1 * 128];
__device__ float g_h1    [NODES1 * 128];
__device__ float g_score1[NODES1];
__device__ int   g_perm1 [NODES2];
__device__ int   g_inv1  [NODES1];
__device__ float g_h1p   [NODES2 * 128];
__device__ float g_x1    [B_ * 256];
__device__ float g_s2    [NODES2 * 128];
__device__ float g_h2    [NODES2 * 128];
__device__ float g_score2[NODES2];
__device__ int   g_perm2 [NODES3];
__device__ float g_h2p   [NODES3 * 128];
__device__ float g_x2    [B_ * 256];
// transposed, bf16-split weights: [n=128][k=256] K-major (k contiguous)
__device__ __nv_bfloat16 g_wthi1[128 * 256];
__device__ __nv_bfloat16 g_wtlo1[128 * 256];
__device__ __nv_bfloat16 g_wthi2[128 * 256];
__device__ __nv_bfloat16 g_wtlo2[128 * 256];
// CSR scratch
__device__ int g_deg1   [NODES1];
__device__ int g_row1   [NODES1];
__device__ int g_cur1   [NODES1];
__device__ int g_csrc1  [E_];
__device__ int g_deg2   [NODES2];
__device__ int g_row2   [NODES2];
__device__ int g_cur2   [NODES2];
__device__ int g_csrc2  [E_];
__device__ int g_ctr1;
__device__ int g_ctr2;

// ---------------- CSR build: degree histograms ----------------
__global__ void deg1_kernel(const int* __restrict__ dst, int* __restrict__ deg)
{
    int e = blockIdx.x * blockDim.x + threadIdx.x;
    if (e < E_) atomicAdd(&deg[dst[e]], 1);
}
__global__ void deg2_kernel(const int* __restrict__ src, const int* __restrict__ dst,
                            const int* __restrict__ inv, int* __restrict__ deg)
{
    int e = blockIdx.x * blockDim.x + threadIdx.x;
    if (e >= E_) return;
    int ns = inv[src[e]], nd = inv[dst[e]];
    if (ns >= 0 && nd >= 0) atomicAdd(&deg[nd], 1);
}

// ---------------- segment allocator: per-block scan + single global atomic -------------------
// rowptr[i] gets a contiguous segment of size deg[i]; order across blocks irrelevant.
__global__ __launch_bounds__(256) void alloc_kernel(const int* __restrict__ deg,
                                                    int* __restrict__ rowptr,
                                                    int* __restrict__ cursor,
                                                    int n, int* __restrict__ ctr)
{
    __shared__ int sdata[256];
    __shared__ int sbase;
    int tid = threadIdx.x;
    int i = blockIdx.x * 256 + tid;
    int d = (i < n) ? deg[i] : 0;
    sdata[tid] = d;
    __syncthreads();
    #pragma unroll
    for (int off = 1; off < 256; off <<= 1) {
        int v = (tid >= off) ? sdata[tid - off] : 0;
        __syncthreads();
        sdata[tid] += v;
        __syncthreads();
    }
    if (tid == 255) sbase = atomicAdd(ctr, sdata[255]);
    __syncthreads();
    if (i < n) {
        int p = sbase + sdata[tid] - d;   // exclusive position within block + block base
        rowptr[i] = p;
        cursor[i] = p;
    }
}

// ---------------- scatter edges into CSR ----------------
__global__ void scatter1_kernel(const int* __restrict__ src, const int* __restrict__ dst,
                                int* __restrict__ cursor, int* __restrict__ csrc)
{
    int e = blockIdx.x * blockDim.x + threadIdx.x;
    if (e >= E_) return;
    int p = atomicAdd(&cursor[dst[e]], 1);
    csrc[p] = src[e];
}
__global__ void scatter2_kernel(const int* __restrict__ src, const int* __restrict__ dst,
                                const int* __restrict__ inv,
                                int* __restrict__ cursor, int* __restrict__ csrc)
{
    int e = blockIdx.x * blockDim.x + threadIdx.x;
    if (e >= E_) return;
    int ns = inv[src[e]], nd = inv[dst[e]];
    if (ns < 0 || nd < 0) return;
    int p = atomicAdd(&cursor[nd], 1);
    csrc[p] = ns;
}

// ---------------- CSR aggregation + mean, warp per node (fused meandiv; no memset) ------------
__global__ void agg_csr_kernel(const float* __restrict__ feat, const int* __restrict__ rowptr,
                               const int* __restrict__ deg, const int* __restrict__ csrc,
                               float* __restrict__ s, int n)
{
    int g = blockIdx.x * blockDim.x + threadIdx.x;
    int node = g >> 5, lane = g & 31;
    if (node >= n) return;
    int beg = rowptr[node];
    int cnt = deg[node];
    float4 acc = make_float4(0.f, 0.f, 0.f, 0.f);
    for (int e = beg; e < beg + cnt; e++) {
        int sn = csrc[e];
        float4 v = ((const float4*)(feat + (size_t)sn * 128))[lane];
        acc.x += v.x; acc.y += v.y; acc.z += v.z; acc.w += v.w;
    }
    float c = fmaxf((float)cnt, 1.0f);
    acc.x /= c; acc.y /= c; acc.z /= c; acc.w /= c;
    ((float4*)(s + (size_t)node * 128))[lane] = acc;
}

// ---------------- weight prep: Wt_hi/lo[n][k] = split(W[k][n]), [Wl;Wr] stacked ---------------
__global__ void prep_w_kernel(const float* __restrict__ Wl, const float* __restrict__ Wr,
                              __nv_bfloat16* __restrict__ hi, __nv_bfloat16* __restrict__ lo)
{
    int i = blockIdx.x * blockDim.x + threadIdx.x;  // 128*256
    if (i >= 128 * 256) return;
    int n = i >> 8, k = i & 255;
    float v = (k < 128) ? Wl[k * 128 + n] : Wr[(k - 128) * 128 + n];
    __nv_bfloat16 h = __float2bfloat16(v);
    hi[i] = h;
    lo[i] = __float2bfloat16(v - __bfloat162float(h));
}

// ---------------- wmma bf16 SAGE GEMM + fused score ------------------------------------------
// out = relu([mean|xin] @ [Wl;Wr] + bias); score = tanh(out . w / ||w||)
// 128x128 tile/CTA, 8 warps (4x2 of 32x64 warp tiles), K=256 in 4 chunks of 64.
// Split-bf16 3-product fp32 emulation: Ahi*Bhi + Ahi*Blo + Alo*Bhi.
#define LDA     72
#define SM_BIAS 0                        // 128 floats
#define SM_W    512                      // 128 floats
#define SM_AHI  1024
#define SM_ALO  (SM_AHI + 128 * LDA * 2)
#define SM_BHI  (SM_ALO + 128 * LDA * 2)
#define SM_BLO  (SM_BHI + 128 * LDA * 2)
#define SM_END  (SM_BLO + 128 * LDA * 2)     // 1024 + 73728 = 74752
#define SM_OUT  1024                     // reused post-mainloop: 128 x 132 f32
#define LDO     132

__global__ __launch_bounds__(256, 2)
void sage_wmma_kernel(const float* __restrict__ mean, const float* __restrict__ xin,
                      const __nv_bfloat16* __restrict__ wt_hi,
                      const __nv_bfloat16* __restrict__ wt_lo,
                      const float* __restrict__ bias, const float* __restrict__ pw,
                      float* __restrict__ outp, float* __restrict__ scoreo)
{
    extern __shared__ char smem[];
    float* sbias = (float*)(smem + SM_BIAS);
    float* sw    = (float*)(smem + SM_W);
    __nv_bfloat16* sAhi = (__nv_bfloat16*)(smem + SM_AHI);
    __nv_bfloat16* sAlo = (__nv_bfloat16*)(smem + SM_ALO);
    __nv_bfloat16* sBhi = (__nv_bfloat16*)(smem + SM_BHI);
    __nv_bfloat16* sBlo = (__nv_bfloat16*)(smem + SM_BLO);

    int tid = threadIdx.x;
    int warp = tid >> 5;
    int wy = warp >> 1;
    int wx = warp & 1;
    int row0 = blockIdx.x * 128;

    if (tid < 128) sbias[tid] = bias[tid];
    else if (tid < 256) sw[tid - 128] = pw[tid - 128];

    wmma::fragment<wmma::accumulator, 16, 16, 16, float> acc[2][4];
    #pragma unroll
    for (int mi = 0; mi < 2; mi++)
        #pragma unroll
        for (int nt = 0; nt < 4; nt++) wmma::fill_fragment(acc[mi][nt], 0.0f);

    #pragma unroll 1
    for (int chunk = 0; chunk < 4; chunk++) {
        const float* abase = (chunk < 2) ? mean : xin;
        int acol = (chunk & 1) * 64;
        #pragma unroll
        for (int s = tid; s < 1024; s += 256) {
            int r = s >> 3, kseg = s & 7;
            const float* ap = abase + (size_t)(row0 + r) * 128 + acol + kseg * 8;
            float4 v0 = *(const float4*)ap;
            float4 v1 = *(const float4*)(ap + 4);
            float vv[8] = {v0.x, v0.y, v0.z, v0.w, v1.x, v1.y, v1.z, v1.w};
            unsigned int Hh[4], Ll[4];
            #pragma unroll
            for (int i = 0; i < 4; i++) {
                __nv_bfloat16 h0 = __float2bfloat16(vv[2 * i]);
                __nv_bfloat16 h1 = __float2bfloat16(vv[2 * i + 1]);
                __nv_bfloat16 l0 = __float2bfloat16(vv[2 * i] - __bfloat162float(h0));
                __nv_bfloat16 l1 = __float2bfloat16(vv[2 * i + 1] - __bfloat162float(h1));
                Hh[i] = (unsigned int)__bfloat16_as_ushort(h0)
                      | ((unsigned int)__bfloat16_as_ushort(h1) << 16);
                Ll[i] = (unsigned int)__bfloat16_as_ushort(l0)
                      | ((unsigned int)__bfloat16_as_ushort(l1) << 16);
            }
            *(uint4*)(sAhi + r * LDA + kseg * 8) = make_uint4(Hh[0], Hh[1], Hh[2], Hh[3]);
            *(uint4*)(sAlo + r * LDA + kseg * 8) = make_uint4(Ll[0], Ll[1], Ll[2], Ll[3]);
        }
        #pragma unroll
        for (int s = tid; s < 1024; s += 256) {
            int n = s >> 3, kseg = s & 7;
            size_t gi = (size_t)n * 256 + chunk * 64 + kseg * 8;
            *(uint4*)(sBhi + n * LDA + kseg * 8) = *(const uint4*)(wt_hi + gi);
            *(uint4*)(sBlo + n * LDA + kseg * 8) = *(const uint4*)(wt_lo + gi);
        }
        __syncthreads();

        #pragma unroll
        for (int ks = 0; ks < 4; ks++) {
            wmma::fragment<wmma::matrix_a, 16, 16, 16, __nv_bfloat16, wmma::row_major> ahi[2], alo[2];
            #pragma unroll
            for (int mi = 0; mi < 2; mi++) {
                wmma::load_matrix_sync(ahi[mi], sAhi + (wy * 32 + mi * 16) * LDA + ks * 16, LDA);
                wmma::load_matrix_sync(alo[mi], sAlo + (wy * 32 + mi * 16) * LDA + ks * 16, LDA);
            }
            #pragma unroll
            for (int nt = 0; nt < 4; nt++) {
                wmma::fragment<wmma::matrix_b, 16, 16, 16, __nv_bfloat16, wmma::col_major> bhi, blo;
                wmma::load_matrix_sync(bhi, sBhi + (wx * 64 + nt * 16) * LDA + ks * 16, LDA);
                wmma::load_matrix_sync(blo, sBlo + (wx * 64 + nt * 16) * LDA + ks * 16, LDA);
                #pragma unroll
                for (int mi = 0; mi < 2; mi++) {
                    wmma::mma_sync(acc[mi][nt], ahi[mi], bhi, acc[mi][nt]);
                    wmma::mma_sync(acc[mi][nt], ahi[mi], blo, acc[mi][nt]);
                    wmma::mma_sync(acc[mi][nt], alo[mi], bhi, acc[mi][nt]);
                }
            }
        }
        __syncthreads();
    }

    // ---- epilogue: dump accs to SMEM; bias+relu; store; fused score ----
    float* sout = (float*)(smem + SM_OUT);
    #pragma unroll
    for (int mi = 0; mi < 2; mi++)
        #pragma unroll
        for (int nt = 0; nt < 4; nt++)
            wmma::store_matrix_sync(sout + (wy * 32 + mi * 16) * LDO + wx * 64 + nt * 16,
                                    acc[mi][nt], LDO, wmma::mem_row_major);
    __syncthreads();

    int tr = tid >> 1;
    int tc = (tid & 1) * 64;
    float dot = 0.0f, nrm = 0.0f;
    #pragma unroll
    for (int q = 0; q < 16; q++) {
        int col = tc + q * 4;
        float4 v = *(float4*)&sout[tr * LDO + col];
        float4 bb = *(float4*)&sbias[col];
        float4 wv = *(float4*)&sw[col];
        v.x = fmaxf(v.x + bb.x, 0.0f);
        v.y = fmaxf(v.y + bb.y, 0.0f);
        v.z = fmaxf(v.z + bb.z, 0.0f);
        v.w = fmaxf(v.w + bb.w, 0.0f);
        dot += v.x * wv.x + v.y * wv.y + v.z * wv.z + v.w * wv.w;
        nrm += wv.x * wv.x + wv.y * wv.y + wv.z * wv.z + wv.w * wv.w;
        *(float4*)&outp[(size_t)(row0 + tr) * 128 + col] = v;
    }
    dot += __shfl_xor_sync(0xFFFFFFFFu, dot, 1);
    nrm += __shfl_xor_sync(0xFFFFFFFFu, nrm, 1);
    if ((tid & 1) == 0) scoreo[row0 + tr] = tanhf(dot * rsqrtf(nrm));
}

// ---------------- TopK pool: per-graph bitonic sort (desc score, asc idx), compact by idx ----
__global__ __launch_bounds__(1024) void topk_kernel(
    const float* __restrict__ score, int* __restrict__ perm, int* __restrict__ inv,
    int n_per, int K)
{
    __shared__ unsigned long long keys[1024];
    __shared__ int keep[1024];
    __shared__ int scan[1024];
    int tid = threadIdx.x, b = blockIdx.x;

    float sc = (tid < n_per) ? score[b * n_per + tid] : __int_as_float(0xFF800000);
    unsigned int bits = __float_as_uint(sc);
    unsigned int u = (bits & 0x80000000u) ? ~bits : (bits | 0x80000000u);
    keys[tid] = ((unsigned long long)u << 32) | (unsigned int)(1023 - tid);
    keep[tid] = 0;
    __syncthreads();

    for (int k = 2; k <= 1024; k <<= 1) {
        for (int j = k >> 1; j > 0; j >>= 1) {
            int ixj = tid ^ j;
            if (ixj > tid) {
                unsigned long long a = keys[tid], c = keys[ixj];
                bool up = ((tid & k) == 0);
                bool sw = up ? (a < c) : (a > c);
                if (sw) { keys[tid] = c; keys[ixj] = a; }
            }
            __syncthreads();
        }
    }

    if (tid < K) {
        int idx = 1023 - (int)(keys[tid] & 0xFFFFFFFFu);
        keep[idx] = 1;
    }
    __syncthreads();

    int v = keep[tid];
    scan[tid] = v;
    __syncthreads();
    for (int off = 1; off < 1024; off <<= 1) {
        int t = (tid >= off) ? scan[tid - off] : 0;
        __syncthreads();
        scan[tid] += t;
        __syncthreads();
    }

    if (tid < n_per) {
        int old = b * n_per + tid;
        if (v) {
            int newid = b * K + (scan[tid] - 1);
            perm[newid] = old;
            if (inv) inv[old] = newid;
        } else if (inv) {
            inv[old] = -1;
        }
    }
}

// ---------------- gate: hp[new] = h[perm[new]] * score[perm[new]] -----------------------------
__global__ void gate_kernel(const float* __restrict__ h, const float* __restrict__ score,
                            const int* __restrict__ perm, float* __restrict__ hp, int total)
{
    int g = blockIdx.x * blockDim.x + threadIdx.x;
    int nid = g >> 5, lane = g & 31;
    if (nid >= total) return;
    int old = perm[nid];
    float sc = score[old];
    float4 v = ((const float4*)(h + (size_t)old * 128))[lane];
    v.x *= sc; v.y *= sc; v.z *= sc; v.w *= sc;
    ((float4*)(hp + (size_t)nid * 128))[lane] = v;
}

// ---------------- readout: [mean over K | max over K] per graph ------------------------------
__global__ void readout_kernel(const float* __restrict__ hp, float* __restrict__ xout, int K)
{
    __shared__ float ss[4][128], sm[4][128];
    int b = blockIdx.x;
    int tid = threadIdx.x;          // 512 threads
    int f = tid & 127, ty = tid >> 7;
    float sum = 0.0f, mx = __int_as_float(0xFF800000);
    for (int r = ty; r < K; r += 4) {
        float v = hp[((size_t)(b * K + r)) * 128 + f];
        sum += v;
        mx = fmaxf(mx, v);
    }
    ss[ty][f] = sum; sm[ty][f] = mx;
    __syncthreads();
    if (ty == 0) {
        float s = ss[0][f] + ss[1][f] + ss[2][f] + ss[3][f];
        float m = fmaxf(fmaxf(sm[0][f], sm[1][f]), fmaxf(sm[2][f], sm[3][f]));
        xout[b * 256 + f] = s / (float)K;
        xout[b * 256 + 128 + f] = m;
    }
}

// ---------------- final MLP: out = relu((x1+x2)@fW1+fb1) @ fW2 + fb2 --------------------------
__global__ void mlp_kernel(const float* __restrict__ x1, const float* __restrict__ x2,
                           const float* __restrict__ fW1, const float* __restrict__ fb1,
                           const float* __restrict__ fW2, const float* __restrict__ fb2,
                           float* __restrict__ out)
{
    __shared__ float row[256];
    __shared__ float zs[128];
    int b = blockIdx.x, t = threadIdx.x;
    row[t]       = x1[b * 256 + t]       + x2[b * 256 + t];
    row[t + 128] = x1[b * 256 + 128 + t] + x2[b * 256 + 128 + t];
    __syncthreads();
    float acc = fb1[t];
    #pragma unroll 8
    for (int k = 0; k < 256; k++) acc += row[k] * fW1[k * 128 + t];
    zs[t] = fmaxf(acc, 0.0f);
    __syncthreads();
    if (t < 10) {
        float o = fb2[t];
        #pragma unroll 8
        for (int k = 0; k < 128; k++) o += zs[k] * fW2[k * 10 + t];
        out[b * 10 + t] = o;
    }
}

// ---------------- host orchestration ----------------------------------------------------------
extern "C" void kernel_launch(void* const* d_in, const int* in_sizes, int n_in,
                              void* d_out, int out_size)
{
    (void)in_sizes; (void)n_in; (void)out_size;
    const float* x   = (const float*)d_in[0];
    const int*   ei  = (const int*)d_in[1];
    const float* Wl1 = (const float*)d_in[3];
    const float* bl1 = (const float*)d_in[4];
    const float* Wr1 = (const float*)d_in[5];
    const float* Wl2 = (const float*)d_in[6];
    const float* bl2 = (const float*)d_in[7];
    const float* Wr2 = (const float*)d_in[8];
    const float* pw1 = (const float*)d_in[9];
    const float* pw2 = (const float*)d_in[10];
    const float* fW1 = (const float*)d_in[11];
    const float* fb1 = (const float*)d_in[12];
    const float* fW2 = (const float*)d_in[13];
    const float* fb2 = (const float*)d_in[14];
    float* out = (float*)d_out;

    const int* src = ei;
    const int* dst = ei + E_;

    float *ps, *ph1, *psc1, *ph1p, *px1, *ps2, *ph2, *psc2, *ph2p, *px2;
    int *pperm1, *pinv1, *pperm2;
    int *pdeg1, *prow1, *pcur1, *pcsrc1, *pdeg2, *prow2, *pcur2, *pcsrc2, *pctr1, *pctr2;
    __nv_bfloat16 *pwh1, *pwl1_, *pwh2, *pwl2_;
    cudaGetSymbolAddress((void**)&ps,     g_s);
    cudaGetSymbolAddress((void**)&ph1,    g_h1);
    cudaGetSymbolAddress((void**)&psc1,   g_score1);
    cudaGetSymbolAddress((void**)&pperm1, g_perm1);
    cudaGetSymbolAddress((void**)&pinv1,  g_inv1);
    cudaGetSymbolAddress((void**)&ph1p,   g_h1p);
    cudaGetSymbolAddress((void**)&px1,    g_x1);
    cudaGetSymbolAddress((void**)&ps2,    g_s2);
    cudaGetSymbolAddress((void**)&ph2,    g_h2);
    cudaGetSymbolAddress((void**)&psc2,   g_score2);
    cudaGetSymbolAddress((void**)&pperm2, g_perm2);
    cudaGetSymbolAddress((void**)&ph2p,   g_h2p);
    cudaGetSymbolAddress((void**)&px2,    g_x2);
    cudaGetSymbolAddress((void**)&pwh1,   g_wthi1);
    cudaGetSymbolAddress((void**)&pwl1_,  g_wtlo1);
    cudaGetSymbolAddress((void**)&pwh2,   g_wthi2);
    cudaGetSymbolAddress((void**)&pwl2_,  g_wtlo2);
    cudaGetSymbolAddress((void**)&pdeg1,  g_deg1);
    cudaGetSymbolAddress((void**)&prow1,  g_row1);
    cudaGetSymbolAddress((void**)&pcur1,  g_cur1);
    cudaGetSymbolAddress((void**)&pcsrc1, g_csrc1);
    cudaGetSymbolAddress((void**)&pdeg2,  g_deg2);
    cudaGetSymbolAddress((void**)&prow2,  g_row2);
    cudaGetSymbolAddress((void**)&pcur2,  g_cur2);
    cudaGetSymbolAddress((void**)&pcsrc2, g_csrc2);
    cudaGetSymbolAddress((void**)&pctr1,  g_ctr1);
    cudaGetSymbolAddress((void**)&pctr2,  g_ctr2);

    cudaFuncSetAttribute(sage_wmma_kernel,
                         cudaFuncAttributeMaxDynamicSharedMemorySize, SM_END);

    // zero degree histograms + segment counters (tiny)
    cudaMemsetAsync(pdeg1, 0, sizeof(int) * NODES1);
    cudaMemsetAsync(pdeg2, 0, sizeof(int) * NODES2);
    cudaMemsetAsync(pctr1, 0, sizeof(int));
    cudaMemsetAsync(pctr2, 0, sizeof(int));

    // weight prep
    prep_w_kernel<<<128, 256>>>(Wl1, Wr1, pwh1, pwl1_);
    prep_w_kernel<<<128, 256>>>(Wl2, Wr2, pwh2, pwl2_);

    // ---- layer 1: CSR build (no scan: block-aggregated segment allocator) + gather-agg ----
    deg1_kernel<<<(E_ + 255) / 256, 256>>>(dst, pdeg1);
    alloc_kernel<<<(NODES1 + 255) / 256, 256>>>(pdeg1, prow1, pcur1, NODES1, pctr1);
    scatter1_kernel<<<(E_ + 255) / 256, 256>>>(src, dst, pcur1, pcsrc1);
    agg_csr_kernel<<<(NODES1 * 32) / 256, 256>>>(x, prow1, pdeg1, pcsrc1, ps, NODES1);
    sage_wmma_kernel<<<NODES1 / 128, 256, SM_END>>>(ps, x, pwh1, pwl1_, bl1, pw1, ph1, psc1);
    topk_kernel<<<B_, 1024>>>(psc1, pperm1, pinv1, N_, K1_);
    gate_kernel<<<(NODES2 * 32) / 256, 256>>>(ph1, psc1, pperm1, ph1p, NODES2);
    readout_kernel<<<B_, 512>>>(ph1p, px1, K1_);

    // ---- layer 2: CSR build (masked+relabelled) + gather-agg ----
    deg2_kernel<<<(E_ + 255) / 256, 256>>>(src, dst, pinv1, pdeg2);
    alloc_kernel<<<(NODES2 + 255) / 256, 256>>>(pdeg2, prow2, pcur2, NODES2, pctr2);
    scatter2_kernel<<<(E_ + 255) / 256, 256>>>(src, dst, pinv1, pcur2, pcsrc2);
    agg_csr_kernel<<<(NODES2 * 32) / 256, 256>>>(ph1p, prow2, pdeg2, pcsrc2, ps2, NODES2);
    sage_wmma_kernel<<<NODES2 / 128, 256, SM_END>>>(ps2, ph1p, pwh2, pwl2_, bl2, pw2, ph2, psc2);
    topk_kernel<<<B_, 1024>>>(psc2, pperm2, (int*)0, K1_, K2_);
    gate_kernel<<<(NODES3 * 32) / 256, 256>>>(ph2, psc2, pperm2, ph2p, NODES3);
    readout_kernel<<<B_, 512>>>(ph2p, px2, K2_);

    // ---- head ----
    mlp_kernel<<<B_, 128>>>(px1, px2, fW1, fb1, fW2, fb2, out);
}